// round 4
// baseline (speedup 1.0000x reference)
#include <cuda_runtime.h>
#include <math_constants.h>

#define TOPK 9
#define BINS 32            // 32x32 grid over [0,1024)^2, cell = 32px
#define NBINS (BINS * BINS)
#define INV_CELL 0.03125f  // 1/32
#define MAXN 131072
#define MAXG 4096
#define S 4                // slices per GT
#define MT 256             // threads per slice block

// ---------------- device scratch (no allocs allowed) ----------------
// Zero at module load; merge_kernel's tail re-zeros mutable state per replay.
__device__ int      g_bin_count[NBINS];
__device__ int      g_bin_start[NBINS + 1];
__device__ int      g_bin_cursor[NBINS];
__device__ float4   g_sorted[MAXN];
__device__ int      g_sorted_idx[MAXN];
__device__ unsigned g_maxw_bits, g_maxh_bits;
__device__ float    g_pv[MAXG * S * TOPK];   // partial top-9 values
__device__ int      g_pi[MAXG * S * TOPK];   // partial top-9 indices

// ---------------- pass 1: zero w + smem histogram + max extents ----------------
__global__ __launch_bounds__(256) void count_kernel(
    const float* __restrict__ preds, float* __restrict__ w, int N)
{
    __shared__ int hist[NBINS];
    __shared__ unsigned s_mw, s_mh;
    int tid = threadIdx.x;
#pragma unroll
    for (int i = 0; i < NBINS / 256; i++) hist[tid + i * 256] = 0;
    if (tid == 0) { s_mw = 0u; s_mh = 0u; }
    __syncthreads();

    int n = blockIdx.x * 256 + tid;
    unsigned mw = 0u, mh = 0u;
    if (n < N) {
        w[n] = 0.0f;   // replaces a memset launch
        float4 b = ((const float4*)preds)[n];
        int bx = min(BINS - 1, (int)(b.x * INV_CELL));
        int by = min(BINS - 1, (int)(b.y * INV_CELL));
        atomicAdd(&hist[by * BINS + bx], 1);
        mw = __float_as_uint(b.z - b.x);   // sizes > 0: uint cmp == float cmp
        mh = __float_as_uint(b.w - b.y);
    }
#pragma unroll
    for (int off = 16; off > 0; off >>= 1) {
        mw = max(mw, __shfl_down_sync(0xffffffffu, mw, off));
        mh = max(mh, __shfl_down_sync(0xffffffffu, mh, off));
    }
    if ((tid & 31) == 0) { atomicMax(&s_mw, mw); atomicMax(&s_mh, mh); }
    __syncthreads();

#pragma unroll
    for (int i = 0; i < NBINS / 256; i++) {
        int c = hist[tid + i * 256];
        if (c > 0) atomicAdd(&g_bin_count[tid + i * 256], c);
    }
    if (tid == 0) {
        atomicMax(&g_maxw_bits, s_mw);
        atomicMax(&g_maxh_bits, s_mh);
    }
}

// ---------------- pass 2: exclusive scan over 1024 bins ----------------
__global__ __launch_bounds__(NBINS) void scan_kernel() {
    __shared__ int sh[NBINS];
    int t = threadIdx.x;
    int c = g_bin_count[t];
    sh[t] = c;
    __syncthreads();
    for (int off = 1; off < NBINS; off <<= 1) {
        int v = (t >= off) ? sh[t - off] : 0;
        __syncthreads();
        sh[t] += v;
        __syncthreads();
    }
    int incl = sh[t];
    g_bin_start[t] = incl - c;
    g_bin_cursor[t] = incl - c;
    if (t == NBINS - 1) g_bin_start[NBINS] = incl;
}

// ---------------- pass 3: scatter preds into bin-sorted order ----------------
__global__ __launch_bounds__(256) void scatter_kernel(const float* __restrict__ preds, int N) {
    int n = blockIdx.x * 256 + threadIdx.x;
    if (n >= N) return;
    float4 b = ((const float4*)preds)[n];
    int bx = min(BINS - 1, (int)(b.x * INV_CELL));
    int by = min(BINS - 1, (int)(b.y * INV_CELL));
    int pos = atomicAdd(&g_bin_cursor[by * BINS + bx], 1);
    g_sorted[pos] = b;
    g_sorted_idx[pos] = n;
}

// ---------------------------------------------------------------------------
// Phase 1: per-(GT, slice) partial top-9 over binned candidates.
//   key = log(iou) + 0.25*log(sigmoid(cls))   (monotone in cls^0.2 * iou^0.8)
// Every GT has >>9 positive-IoU preds, so zero-IoU pairs never rank.
// ---------------------------------------------------------------------------
__global__ __launch_bounds__(MT) void topk_kernel(
    const float* __restrict__ cls,     // [N,C]
    const float* __restrict__ gtb,     // [G,4]
    const int*   __restrict__ labels,  // [G]
    int C)
{
    const int g     = blockIdx.x >> 2;       // S == 4
    const int slice = blockIdx.x & 3;
    const int tid   = threadIdx.x;
    const int lane  = tid & 31;
    const int warp  = tid >> 5;
    const int NW    = MT / 32;                // 8 warps

    const float gx1 = gtb[g * 4 + 0];
    const float gy1 = gtb[g * 4 + 1];
    const float gx2 = gtb[g * 4 + 2];
    const float gy2 = gtb[g * 4 + 3];
    const float garea = (gx2 - gx1) * (gy2 - gy1);
    const int lab = labels[g];

    const float maxw = __uint_as_float(g_maxw_bits);
    const float maxh = __uint_as_float(g_maxh_bits);

    int bx0 = max(0, (int)floorf((gx1 - maxw) * INV_CELL));
    int bx1 = min(BINS - 1, (int)(gx2 * INV_CELL));
    int by0 = max(0, (int)floorf((gy1 - maxh) * INV_CELL));
    int by1 = min(BINS - 1, (int)(gy2 * INV_CELL));

    float kv[TOPK];
    int   ki[TOPK];
#pragma unroll
    for (int i = 0; i < TOPK; i++) { kv[i] = -CUDART_INF_F; ki[i] = 0x7fffffff; }
    float vmin = -CUDART_INF_F;

    for (int by = by0; by <= by1; by++) {
        int s = g_bin_start[by * BINS + bx0];
        int e = g_bin_start[by * BINS + bx1 + 1];
        for (int i = s + slice * MT + tid; i < e; i += MT * S) {
            float4 b = g_sorted[i];
            float iw = fminf(b.z, gx2) - fmaxf(b.x, gx1);
            float ih = fminf(b.w, gy2) - fmaxf(b.y, gy1);
            if (iw > 0.0f && ih > 0.0f) {
                int n = g_sorted_idx[i];
                float inter = iw * ih;
                float uni = fmaxf((b.z - b.x) * (b.w - b.y) + garea - inter, 1e-6f);
                float iou = __fdividef(inter, uni);
                float x   = __ldg(&cls[(long long)n * C + lab]);
                float key = __logf(iou) - 0.25f * __logf(1.0f + __expf(-x));
                if (key > vmin) {
                    int am = 0; float mv = kv[0];
#pragma unroll
                    for (int j = 1; j < TOPK; j++) if (kv[j] < mv) { mv = kv[j]; am = j; }
#pragma unroll
                    for (int j = 0; j < TOPK; j++) if (j == am) { kv[j] = key; ki[j] = n; }
                    vmin = kv[0];
#pragma unroll
                    for (int j = 1; j < TOPK; j++) vmin = fminf(vmin, kv[j]);
                }
            }
        }
    }

    // ---- stage 1: per-warp top-9 via 9 argmax rounds ----
    __shared__ float sv2[NW * TOPK];
    __shared__ int   si2[NW * TOPK];

    for (int round = 0; round < TOPK; round++) {
        float bv = -CUDART_INF_F; int bi = 0x7fffffff; int bs = 0;
#pragma unroll
        for (int j = 0; j < TOPK; j++)
            if (kv[j] > bv) { bv = kv[j]; bi = ki[j]; bs = j; }
        float rv = bv; int rix = bi; int rl = lane;
#pragma unroll
        for (int off = 16; off > 0; off >>= 1) {
            float ov = __shfl_down_sync(0xffffffffu, rv, off);
            int   oi = __shfl_down_sync(0xffffffffu, rix, off);
            int   ol = __shfl_down_sync(0xffffffffu, rl, off);
            if (ov > rv || (ov == rv && oi < rix)) { rv = ov; rix = oi; rl = ol; }
        }
        int wlane = __shfl_sync(0xffffffffu, rl, 0);
        if (lane == 0) {
            sv2[warp * TOPK + round] = rv;
            si2[warp * TOPK + round] = rix;
        }
        if (lane == wlane) kv[bs] = -CUDART_INF_F;
    }
    __syncthreads();

    // ---- stage 2: warp 0 merges 72 entries -> slice top-9 -> scratch ----
    const int TOT = NW * TOPK;   // 72
    if (warp == 0) {
        int base = (g * S + slice) * TOPK;
        for (int round = 0; round < TOPK; round++) {
            float bv = -CUDART_INF_F; int bi = 0x7fffffff; int bp = -1;
            for (int j = lane; j < TOT; j += 32) {
                float v = sv2[j];
                if (v > bv || (v == bv && si2[j] < bi)) { bv = v; bi = si2[j]; bp = j; }
            }
#pragma unroll
            for (int off = 16; off > 0; off >>= 1) {
                float ov = __shfl_down_sync(0xffffffffu, bv, off);
                int   oi = __shfl_down_sync(0xffffffffu, bi, off);
                int   op = __shfl_down_sync(0xffffffffu, bp, off);
                if (ov > bv || (ov == bv && oi < bi)) { bv = ov; bi = oi; bp = op; }
            }
            if (lane == 0) {
                g_pv[base + round] = bv;
                g_pi[base + round] = bi;
                if (bp >= 0) sv2[bp] = -CUDART_INF_F;
            }
            __syncwarp();
        }
    }
}

// ---------------------------------------------------------------------------
// Phase 2: one warp per GT — merge S*9=36 partials -> top-9 -> stats -> scatter
// Tail: reset binning counters/extents for next graph replay.
// ---------------------------------------------------------------------------
__global__ __launch_bounds__(32) void merge_kernel(
    const float* __restrict__ points,  // [N,2]
    const float* __restrict__ gtb,     // [G,4]
    float* __restrict__ w)             // [N] zeroed by count_kernel
{
    const int g    = blockIdx.x;
    const int lane = threadIdx.x;
    const int base = g * S * TOPK;
    const int TOT  = S * TOPK;   // 36

    // two entries per lane (lane, lane+32); only lane < 4 has a second entry
    float v0 = (lane < TOT) ? g_pv[base + lane] : -CUDART_INF_F;
    int   i0 = (lane < TOT) ? g_pi[base + lane] : 0x7fffffff;
    float v1 = (lane + 32 < TOT) ? g_pv[base + lane + 32] : -CUDART_INF_F;
    int   i1 = (lane + 32 < TOT) ? g_pi[base + lane + 32] : 0x7fffffff;

    int fidx[TOPK];
    for (int round = 0; round < TOPK; round++) {
        // local best of the two slots (value desc, index asc)
        bool first = (v0 > v1) || (v0 == v1 && i0 < i1);
        float bv = first ? v0 : v1;
        int   bi = first ? i0 : i1;
        int   bc = lane * 2 + (first ? 0 : 1);
#pragma unroll
        for (int off = 16; off > 0; off >>= 1) {
            float ov = __shfl_down_sync(0xffffffffu, bv, off);
            int   oi = __shfl_down_sync(0xffffffffu, bi, off);
            int   oc = __shfl_down_sync(0xffffffffu, bc, off);
            if (ov > bv || (ov == bv && oi < bi)) { bv = ov; bi = oi; bc = oc; }
        }
        int wc = __shfl_sync(0xffffffffu, bc, 0);
        fidx[round] = __shfl_sync(0xffffffffu, bi, 0);
        if (lane == (wc >> 1)) {
            if ((wc & 1) == 0) v0 = -CUDART_INF_F; else v1 = -CUDART_INF_F;
        }
    }

    // ---- fused stats: mean/cov/inverse/maha/valid/scatter-max ----
    int   id = 0x7fffffff;
    float px = 0.0f, py = 0.0f;
    bool  ok = false;
    if (lane < TOPK) {
        id = fidx[lane];
        if (id != 0x7fffffff) {
            ok = true;
            px = points[(long long)id * 2 + 0];
            py = points[(long long)id * 2 + 1];
        }
    }
    float vx = ok ? px : 0.0f, vy = ok ? py : 0.0f;
#pragma unroll
    for (int off = 16; off > 0; off >>= 1) {
        vx += __shfl_down_sync(0xffffffffu, vx, off);
        vy += __shfl_down_sync(0xffffffffu, vy, off);
    }
    const float inv9 = 1.0f / 9.0f;
    float mx = __shfl_sync(0xffffffffu, vx, 0) * inv9;
    float my = __shfl_sync(0xffffffffu, vy, 0) * inv9;

    float dx = ok ? (px - mx) : 0.0f;
    float dy = ok ? (py - my) : 0.0f;
    float sa = dx * dx, sb = dx * dy, sd = dy * dy;
#pragma unroll
    for (int off = 16; off > 0; off >>= 1) {
        sa += __shfl_down_sync(0xffffffffu, sa, off);
        sb += __shfl_down_sync(0xffffffffu, sb, off);
        sd += __shfl_down_sync(0xffffffffu, sd, off);
    }
    float a = __shfl_sync(0xffffffffu, sa, 0) * inv9;
    float b = __shfl_sync(0xffffffffu, sb, 0) * inv9;
    float d = __shfl_sync(0xffffffffu, sd, 0) * inv9;
    float rdn = 1.0f / ((a * d - b * b) + 1e-10f);

    if (ok) {
        float gx1 = gtb[g * 4 + 0];
        float gy1 = gtb[g * 4 + 1];
        float gx2 = gtb[g * 4 + 2];
        float gy2 = gtb[g * 4 + 3];
        float maha = (d * dx * dx - 2.0f * b * dx * dy + a * dy * dy) * rdn;
        float wv = __expf(-0.5f * maha);
        // cy = px (coord 0), cx = py (coord 1); EPS = 1e-10
        bool valid = (py - gx1 > 1e-10f) && (px - gy1 > 1e-10f) &&
                     (gx2 - py > 1e-10f) && (gy2 - px > 1e-10f);
        if (valid && wv > 0.0f)
            atomicMax((int*)&w[id], __float_as_int(wv));  // wv >= 0
    }

    // ---- tail: reset binning state for next launch/replay ----
    for (int t = g * 32 + lane; t < NBINS; t += gridDim.x * 32)
        g_bin_count[t] = 0;
    if (g == 0 && lane == 0) { g_maxw_bits = 0u; g_maxh_bits = 0u; }
}

extern "C" void kernel_launch(void* const* d_in, const int* in_sizes, int n_in,
                              void* d_out, int out_size) {
    const float* points = (const float*)d_in[0];   // [N,2]
    const float* cls    = (const float*)d_in[1];   // [N,C]
    const float* preds  = (const float*)d_in[2];   // [N,4]
    const float* gtb    = (const float*)d_in[3];   // [G,4]
    const int*   labels = (const int*)d_in[4];     // [G]

    int N = in_sizes[2] / 4;
    int C = in_sizes[1] / N;
    int G = in_sizes[4];
    float* w = (float*)d_out;

    count_kernel<<<(N + 255) / 256, 256>>>(preds, w, N);
    scan_kernel<<<1, NBINS>>>();
    scatter_kernel<<<(N + 255) / 256, 256>>>(preds, N);
    topk_kernel<<<G * S, MT>>>(cls, gtb, labels, C);
    merge_kernel<<<G, 32>>>(points, gtb, w);
}